// round 10
// baseline (speedup 1.0000x reference)
#include <cuda_runtime.h>
#include <cuda_fp16.h>

#define D 64
#define MAXN 100000
#define MAXE 1200000
#define EPS 1e-12f

// Scratch (device globals — no allocation allowed in kernel_launch)
__device__ __half g_nh[(size_t)MAXN * D];  // normalized features, fp16, 12.8 MB
__device__ float  g_norm[MAXN];            // per-node L2 norm
__device__ float  g_psum[MAXN];            // per-dst softmax denominator

// ---------------------------------------------------------------------------
// K1 (ILP=2): L2-normalize two nodes per thread-group-slot. 16 lanes per
//     node, float4 per lane; two independent chains interleaved to hide
//     load + shfl latency. Stores nh fp16 + norm scalar, zeroes psum.
// ---------------------------------------------------------------------------
__global__ void k_norm(const float* __restrict__ feat, int N, int nhalf) {
    int t = blockIdx.x * blockDim.x + threadIdx.x;
    int n1 = t >> 4, sub = t & 15;
    if (n1 >= nhalf) return;
    int n2 = n1 + nhalf;
    bool has2 = (n2 < N);

    float4 v1 = __ldg((const float4*)(feat + (size_t)n1 * D) + sub);
    float4 v2 = has2 ? __ldg((const float4*)(feat + (size_t)n2 * D) + sub)
                     : make_float4(0.f, 0.f, 0.f, 0.f);

    float s1 = v1.x * v1.x + v1.y * v1.y + v1.z * v1.z + v1.w * v1.w;
    float s2 = v2.x * v2.x + v2.y * v2.y + v2.z * v2.z + v2.w * v2.w;
    #pragma unroll
    for (int o = 8; o; o >>= 1) {
        s1 += __shfl_xor_sync(0xffffffffu, s1, o);
        s2 += __shfl_xor_sync(0xffffffffu, s2, o);
    }
    float nr1 = fmaxf(sqrtf(s1), EPS), in1 = 1.0f / nr1;
    float nr2 = fmaxf(sqrtf(s2), EPS), in2 = 1.0f / nr2;

    __half2 h0 = __floats2half2_rn(v1.x * in1, v1.y * in1);
    __half2 h1 = __floats2half2_rn(v1.z * in1, v1.w * in1);
    ((uint2*)(g_nh + (size_t)n1 * D))[sub] =
        make_uint2(*(const unsigned*)&h0, *(const unsigned*)&h1);
    if (sub == 0) { g_norm[n1] = nr1; g_psum[n1] = 0.0f; }

    if (has2) {
        __half2 g0 = __floats2half2_rn(v2.x * in2, v2.y * in2);
        __half2 g1 = __floats2half2_rn(v2.z * in2, v2.w * in2);
        ((uint2*)(g_nh + (size_t)n2 * D))[sub] =
            make_uint2(*(const unsigned*)&g0, *(const unsigned*)&g1);
        if (sub == 0) { g_norm[n2] = nr2; g_psum[n2] = 0.0f; }
    }
}

// ---------------------------------------------------------------------------
// K2 (fused edge pass, ILP=4): 16 lanes per edge-quad; each thread owns 4
//     independent edges (e, e+q, e+2q, e+3q). All gathers front-batched for
//     MLP=~10/thread; four interleaved shfl chains. Per edge:
//     - gather nh[src], nh[dst] fp16 (L2-resident)
//     - 16-lane shfl dot; w = exp(beta*dot)  (max-pass skipped: shift-
//       invariant softmax, |beta*cos| <= |beta| so exp is safe)
//     - message from registers: feat[src] = norm[src]*nh[src]
//     - red.global.add.v4.f32 into out[dst]; lane0 red of w into psum[dst]
//     Softmax division hoisted to K3: out_i = (sum w*feat) / (sum w).
// ---------------------------------------------------------------------------
__global__ void k_edge(const int* __restrict__ src, const int* __restrict__ dst,
                       const float* __restrict__ beta,
                       float* __restrict__ out, int E, int q) {
    int t = blockIdx.x * blockDim.x + threadIdx.x;
    int e0 = t >> 4;
    int sub = t & 15;
    if (e0 >= q) return;

    int  eid[4];
    bool ok[4];
    int  s[4], d[4];
    #pragma unroll
    for (int k = 0; k < 4; k++) {
        eid[k] = e0 + k * q;
        ok[k] = (eid[k] < E);
        int ee = ok[k] ? eid[k] : e0;
        s[k] = __ldg(src + ee);
        d[k] = __ldg(dst + ee);
    }

    uint2 pa[4], pb[4];
    float nr[4];
    #pragma unroll
    for (int k = 0; k < 4; k++) {
        pa[k] = __ldg((const uint2*)(g_nh + (size_t)s[k] * D) + sub);
        pb[k] = __ldg((const uint2*)(g_nh + (size_t)d[k] * D) + sub);
        nr[k] = __ldg(&g_norm[s[k]]);
    }
    float bt = __ldg(beta);

    float2 a0[4], a1[4];
    float  p[4];
    #pragma unroll
    for (int k = 0; k < 4; k++) {
        a0[k] = __half22float2(*(const __half2*)&pa[k].x);
        a1[k] = __half22float2(*(const __half2*)&pa[k].y);
        float2 b0 = __half22float2(*(const __half2*)&pb[k].x);
        float2 b1 = __half22float2(*(const __half2*)&pb[k].y);
        p[k] = a0[k].x * b0.x + a0[k].y * b0.y + a1[k].x * b1.x + a1[k].y * b1.y;
    }
    #pragma unroll
    for (int o = 8; o; o >>= 1) {
        #pragma unroll
        for (int k = 0; k < 4; k++) p[k] += __shfl_xor_sync(0xffffffffu, p[k], o);
    }

    float w[4];
    #pragma unroll
    for (int k = 0; k < 4; k++) w[k] = __expf(bt * p[k]);

    #pragma unroll
    for (int k = 0; k < 4; k++) {
        if (!ok[k]) continue;
        float wn = w[k] * nr[k];
        float* adr = out + (size_t)d[k] * D + sub * 4;
        asm volatile("red.global.add.v4.f32 [%0], {%1, %2, %3, %4};"
                     :: "l"(adr), "f"(a0[k].x * wn), "f"(a0[k].y * wn),
                        "f"(a1[k].x * wn), "f"(a1[k].y * wn) : "memory");
    }
    if (sub == 0) {
        #pragma unroll
        for (int k = 0; k < 4; k++) {
            if (!ok[k]) continue;
            asm volatile("red.global.add.f32 [%0], %1;"
                         :: "l"(&g_psum[d[k]]), "f"(w[k]) : "memory");
        }
    }
}

// ---------------------------------------------------------------------------
// K3: per-node normalization: out[i] /= max(psum[i], EPS).
//     Isolated nodes: psum=0 and out row=0 -> stays 0 (matches reference).
// ---------------------------------------------------------------------------
__global__ void k_div(float* __restrict__ out, int N) {
    int t = blockIdx.x * blockDim.x + threadIdx.x;
    int node = t >> 4, sub = t & 15;
    if (node >= N) return;
    float inv = 1.0f / fmaxf(g_psum[node], EPS);
    float4* p = (float4*)(out + (size_t)node * D) + sub;
    float4 v = *p;
    v.x *= inv; v.y *= inv; v.z *= inv; v.w *= inv;
    *p = v;
}

// ---------------------------------------------------------------------------
extern "C" void kernel_launch(void* const* d_in, const int* in_sizes, int n_in,
                              void* d_out, int out_size) {
    const float* feat = (const float*)d_in[0];
    const float* beta = (const float*)d_in[1];
    const int*   src  = (const int*)d_in[2];
    const int*   dst  = (const int*)d_in[3];
    float*       out  = (float*)d_out;

    int N = in_sizes[0] / D;
    int E = in_sizes[2];
    int q = (E + 3) / 4;
    int nhalf = (N + 1) / 2;

    // out accumulates via red.add, so it must start at zero.
    cudaMemsetAsync(out, 0, (size_t)out_size * sizeof(float));

    int norm_threads = nhalf * 16;
    k_norm<<<(norm_threads + 255) / 256, 256>>>(feat, N, nhalf);

    int edge_threads = q * 16;
    k_edge<<<(edge_threads + 255) / 256, 256>>>(src, dst, beta, out, E, q);

    int node_threads = N * 16;
    k_div<<<(node_threads + 255) / 256, 256>>>(out, N);
}

// round 12
// speedup vs baseline: 1.1488x; 1.1488x over previous
#include <cuda_runtime.h>
#include <cuda_fp16.h>

#define D 64
#define MAXN 100000
#define MAXE 1200000
#define EPS 1e-12f

// Scratch (device globals — no allocation allowed in kernel_launch)
__device__ __half g_nh[(size_t)MAXN * D];  // normalized features, fp16, 12.8 MB
__device__ float  g_norm[MAXN];            // per-node L2 norm
__device__ float  g_psum[MAXN];            // per-dst softmax denominator

// ---------------------------------------------------------------------------
// K1 (ILP=2): L2-normalize two nodes per thread. 16 lanes per node, float4
//     per lane; two independent chains interleaved to hide load+shfl latency.
//     Stores nh fp16 + norm scalar, zeroes psum.
// ---------------------------------------------------------------------------
__global__ void k_norm(const float* __restrict__ feat, int N, int nhalf) {
    int t = blockIdx.x * blockDim.x + threadIdx.x;
    int n1 = t >> 4, sub = t & 15;
    if (n1 >= nhalf) return;
    int n2 = n1 + nhalf;
    bool has2 = (n2 < N);

    float4 v1 = __ldg((const float4*)(feat + (size_t)n1 * D) + sub);
    float4 v2 = has2 ? __ldg((const float4*)(feat + (size_t)n2 * D) + sub)
                     : make_float4(0.f, 0.f, 0.f, 0.f);

    float s1 = v1.x * v1.x + v1.y * v1.y + v1.z * v1.z + v1.w * v1.w;
    float s2 = v2.x * v2.x + v2.y * v2.y + v2.z * v2.z + v2.w * v2.w;
    #pragma unroll
    for (int o = 8; o; o >>= 1) {
        s1 += __shfl_xor_sync(0xffffffffu, s1, o);
        s2 += __shfl_xor_sync(0xffffffffu, s2, o);
    }
    float nr1 = fmaxf(sqrtf(s1), EPS), in1 = 1.0f / nr1;
    float nr2 = fmaxf(sqrtf(s2), EPS), in2 = 1.0f / nr2;

    __half2 h0 = __floats2half2_rn(v1.x * in1, v1.y * in1);
    __half2 h1 = __floats2half2_rn(v1.z * in1, v1.w * in1);
    ((uint2*)(g_nh + (size_t)n1 * D))[sub] =
        make_uint2(*(const unsigned*)&h0, *(const unsigned*)&h1);
    if (sub == 0) { g_norm[n1] = nr1; g_psum[n1] = 0.0f; }

    if (has2) {
        __half2 g0 = __floats2half2_rn(v2.x * in2, v2.y * in2);
        __half2 g1 = __floats2half2_rn(v2.z * in2, v2.w * in2);
        ((uint2*)(g_nh + (size_t)n2 * D))[sub] =
            make_uint2(*(const unsigned*)&g0, *(const unsigned*)&g1);
        if (sub == 0) { g_norm[n2] = nr2; g_psum[n2] = 0.0f; }
    }
}

// ---------------------------------------------------------------------------
// K2 (fused edge pass, ILP=2, adjacent pairing): 16 lanes own edges
//     (2g, 2g+1); src/dst indices load as one int2 each. Two independent
//     chains interleaved (measured sweet spot — ILP=4 spills/regresses).
//     Per edge:
//     - gather nh[src], nh[dst] fp16 (L2-resident)
//     - 16-lane shfl dot; w = exp(beta*dot)  (max-pass skipped: shift-
//       invariant softmax, |beta*cos| <= |beta| so exp is safe)
//     - message from registers: feat[src] = norm[src]*nh[src]
//     - red.global.add.v4.f32 into out[dst]; lane0 red of w into psum[dst]
//     Softmax division hoisted to K3: out_i = (sum w*feat) / (sum w).
// ---------------------------------------------------------------------------
__global__ void k_edge(const int* __restrict__ src, const int* __restrict__ dst,
                       const float* __restrict__ beta,
                       float* __restrict__ out, int E, int npair) {
    int t = blockIdx.x * blockDim.x + threadIdx.x;
    int g = t >> 4;
    int sub = t & 15;
    if (g >= npair) return;
    int e1 = g * 2;
    bool has2 = (e1 + 1 < E);

    // --- front-batch all loads (both edges) for maximum MLP ---
    int2 sp = __ldg((const int2*)(src + e1));
    int2 dp = __ldg((const int2*)(dst + e1));
    int s1 = sp.x, d1 = dp.x;
    int s2 = has2 ? sp.y : sp.x;
    int d2 = has2 ? dp.y : dp.x;

    uint2 pa1 = __ldg((const uint2*)(g_nh + (size_t)s1 * D) + sub);
    uint2 pb1 = __ldg((const uint2*)(g_nh + (size_t)d1 * D) + sub);
    uint2 pa2 = __ldg((const uint2*)(g_nh + (size_t)s2 * D) + sub);
    uint2 pb2 = __ldg((const uint2*)(g_nh + (size_t)d2 * D) + sub);
    float n1 = __ldg(&g_norm[s1]);
    float n2 = __ldg(&g_norm[s2]);
    float bt = __ldg(beta);

    float2 a10 = __half22float2(*(const __half2*)&pa1.x);
    float2 a11 = __half22float2(*(const __half2*)&pa1.y);
    float2 b10 = __half22float2(*(const __half2*)&pb1.x);
    float2 b11 = __half22float2(*(const __half2*)&pb1.y);
    float2 a20 = __half22float2(*(const __half2*)&pa2.x);
    float2 a21 = __half22float2(*(const __half2*)&pa2.y);
    float2 b20 = __half22float2(*(const __half2*)&pb2.x);
    float2 b21 = __half22float2(*(const __half2*)&pb2.y);

    // two independent shfl chains — interleaved by the scheduler
    float p1 = a10.x * b10.x + a10.y * b10.y + a11.x * b11.x + a11.y * b11.y;
    float p2 = a20.x * b20.x + a20.y * b20.y + a21.x * b21.x + a21.y * b21.y;
    #pragma unroll
    for (int o = 8; o; o >>= 1) {
        p1 += __shfl_xor_sync(0xffffffffu, p1, o);
        p2 += __shfl_xor_sync(0xffffffffu, p2, o);
    }

    float w1 = __expf(bt * p1);
    float w2 = __expf(bt * p2);
    float wn1 = w1 * n1;
    float wn2 = w2 * n2;

    float* adr1 = out + (size_t)d1 * D + sub * 4;
    asm volatile("red.global.add.v4.f32 [%0], {%1, %2, %3, %4};"
                 :: "l"(adr1), "f"(a10.x * wn1), "f"(a10.y * wn1),
                    "f"(a11.x * wn1), "f"(a11.y * wn1) : "memory");
    if (has2) {
        float* adr2 = out + (size_t)d2 * D + sub * 4;
        asm volatile("red.global.add.v4.f32 [%0], {%1, %2, %3, %4};"
                     :: "l"(adr2), "f"(a20.x * wn2), "f"(a20.y * wn2),
                        "f"(a21.x * wn2), "f"(a21.y * wn2) : "memory");
    }
    if (sub == 0) {
        asm volatile("red.global.add.f32 [%0], %1;"
                     :: "l"(&g_psum[d1]), "f"(w1) : "memory");
        if (has2)
            asm volatile("red.global.add.f32 [%0], %1;"
                         :: "l"(&g_psum[d2]), "f"(w2) : "memory");
    }
}

// ---------------------------------------------------------------------------
// K3: per-node normalization: out[i] /= max(psum[i], EPS).
//     Isolated nodes: psum=0 and out row=0 -> stays 0 (matches reference).
// ---------------------------------------------------------------------------
__global__ void k_div(float* __restrict__ out, int N) {
    int t = blockIdx.x * blockDim.x + threadIdx.x;
    int node = t >> 4, sub = t & 15;
    if (node >= N) return;
    float inv = 1.0f / fmaxf(g_psum[node], EPS);
    float4* p = (float4*)(out + (size_t)node * D) + sub;
    float4 v = *p;
    v.x *= inv; v.y *= inv; v.z *= inv; v.w *= inv;
    *p = v;
}

// ---------------------------------------------------------------------------
extern "C" void kernel_launch(void* const* d_in, const int* in_sizes, int n_in,
                              void* d_out, int out_size) {
    const float* feat = (const float*)d_in[0];
    const float* beta = (const float*)d_in[1];
    const int*   src  = (const int*)d_in[2];
    const int*   dst  = (const int*)d_in[3];
    float*       out  = (float*)d_out;

    int N = in_sizes[0] / D;
    int E = in_sizes[2];
    int npair = (E + 1) / 2;
    int nhalf = (N + 1) / 2;

    // out accumulates via red.add, so it must start at zero.
    cudaMemsetAsync(out, 0, (size_t)out_size * sizeof(float));

    int norm_threads = nhalf * 16;
    k_norm<<<(norm_threads + 255) / 256, 256>>>(feat, N, nhalf);

    int edge_threads = npair * 16;
    k_edge<<<(edge_threads + 255) / 256, 256>>>(src, dst, beta, out, E, npair);

    int node_threads = N * 16;
    k_div<<<(node_threads + 255) / 256, 256>>>(out, N);
}